// round 1
// baseline (speedup 1.0000x reference)
#include <cuda_runtime.h>

#define IMG_SIZE 1280
#define NA 3
#define NC 80
#define BB 16
#define GG 160
#define CP 86              // 6 + NC
#define CC (NA * CP)       // 258
#define PLANE (GG * GG)    // 25600 floats per channel plane

__device__ __forceinline__ float sigmoidf_(float v) {
    return 1.0f / (1.0f + expf(-v));
}

// One thread handles 4 consecutive gx positions (float4 per channel plane).
__global__ __launch_bounds__(256) void anchor_decode_kernel(
    const float* __restrict__ x,
    const float* __restrict__ anchors,
    float* __restrict__ out)
{
    const int nQuads = BB * NA * PLANE / 4;   // 307200
    int tid = blockIdx.x * blockDim.x + threadIdx.x;
    if (tid >= nQuads) return;

    const int quadsPerRow = GG / 4;           // 40
    int gx4  = (tid % quadsPerRow) * 4;
    int rest = tid / quadsPerRow;
    int gy   = rest % GG;
    int ba   = rest / GG;                     // b*NA + a
    int a    = ba % NA;
    int b    = ba / NA;

    const float* base = x + (size_t)(b * CC + a * CP) * PLANE + gy * GG + gx4;

    #define LD4(cp) (*reinterpret_cast<const float4*>(base + (size_t)(cp) * PLANE))

    float4 vx = LD4(0);
    float4 vy = LD4(1);
    float4 vw = LD4(2);
    float4 vh = LD4(3);
    float4 vyaw = LD4(4);
    float4 vconf = LD4(5);

    // argmax over 80 classes, first-max-wins (strict >)
    float bestv[4];
    float besti[4];
    {
        float4 v0 = LD4(6);
        bestv[0] = v0.x; bestv[1] = v0.y; bestv[2] = v0.z; bestv[3] = v0.w;
        besti[0] = besti[1] = besti[2] = besti[3] = 0.0f;
    }
    #pragma unroll 4
    for (int c = 1; c < NC; c++) {
        float4 v = LD4(6 + c);
        float fc = (float)c;
        if (v.x > bestv[0]) { bestv[0] = v.x; besti[0] = fc; }
        if (v.y > bestv[1]) { bestv[1] = v.y; besti[1] = fc; }
        if (v.z > bestv[2]) { bestv[2] = v.z; besti[2] = fc; }
        if (v.w > bestv[3]) { bestv[3] = v.w; besti[3] = fc; }
    }
    #undef LD4

    const float stride = (float)IMG_SIZE / (float)GG;  // 8.0
    float aw = __ldg(&anchors[a * 2 + 0]);
    float ah = __ldg(&anchors[a * 2 + 1]);

    float ox[4] = {vx.x, vx.y, vx.z, vx.w};
    float oy[4] = {vy.x, vy.y, vy.z, vy.w};
    float ow[4] = {vw.x, vw.y, vw.z, vw.w};
    float oh[4] = {vh.x, vh.y, vh.z, vh.w};
    float oyw[4] = {vyaw.x, vyaw.y, vyaw.z, vyaw.w};
    float ocf[4] = {vconf.x, vconf.y, vconf.z, vconf.w};

    float o[28];
    #pragma unroll
    for (int j = 0; j < 4; j++) {
        float sx = sigmoidf_(ox[j]);
        float sy = sigmoidf_(oy[j]);
        o[j * 7 + 0] = floorf((sx + (float)(gx4 + j)) * stride);
        o[j * 7 + 1] = floorf((sy + (float)gy) * stride);
        o[j * 7 + 2] = expf(ow[j]) * aw;
        o[j * 7 + 3] = expf(oh[j]) * ah;
        o[j * 7 + 4] = oyw[j];
        o[j * 7 + 5] = sigmoidf_(ocf[j]);
        o[j * 7 + 6] = besti[j];
    }

    // out[b][a*PLANE + gy*GG + gx][7]; start offset = pos*7 floats, pos % 4 == 0
    // -> offset multiple of 28 floats = 112 bytes: 16B-aligned, 7 float4 stores.
    float* op = out + ((size_t)ba * PLANE + (size_t)gy * GG + gx4) * 7;
    float4* op4 = reinterpret_cast<float4*>(op);
    #pragma unroll
    for (int k = 0; k < 7; k++) {
        op4[k] = make_float4(o[k * 4 + 0], o[k * 4 + 1], o[k * 4 + 2], o[k * 4 + 3]);
    }
}

extern "C" void kernel_launch(void* const* d_in, const int* in_sizes, int n_in,
                              void* d_out, int out_size) {
    const float* x       = (const float*)d_in[0];
    // d_in[1] = target (unused by reference output)
    const float* anchors = (const float*)d_in[2];
    float* out = (float*)d_out;

    const int nQuads = BB * NA * PLANE / 4;   // 307200
    int threads = 256;
    int blocks = (nQuads + threads - 1) / threads;
    anchor_decode_kernel<<<blocks, threads>>>(x, anchors, out);
}